// round 5
// baseline (speedup 1.0000x reference)
#include <cuda_runtime.h>
#include <cuda_fp16.h>

#define NP 8192
#define THREADS 128
#define IPT 4
#define IB (NP / (THREADS * IPT))   // 16 i-blocks (512 i's each)
#define JC 16
#define JCHUNK (NP / JC)            // 512 j's per chunk
#define JP (JCHUNK / 2)             // 256 packed j-pairs

static_assert(IB * THREADS * IPT == NP, "i coverage");
static_assert(JC * JCHUNK == NP, "j coverage");

// Scratch: [i][jc] -> {sum, cnt}; every slot written once per launch.
__device__ float2 g_part[NP * JC];

__device__ __forceinline__ float sqa(float x) {
    float r; asm("sqrt.approx.f32 %0, %1;" : "=f"(r) : "f"(x)); return r;
}

#define T35   0.70020753f   // tan(35 deg)
#define INVT  1.4281480f    // 1/tan(35 deg)
#define TT    0.49029058f   // tan^2(35 deg)

__global__ __launch_bounds__(THREADS)
void pair_kernel(const float2* __restrict__ past, const float2* __restrict__ pos) {
    __shared__ __half2 sx[JP], sy[JP];   // sx[m] = {x(2m), x(2m+1)}
    const int ib = blockIdx.x;
    const int jc = blockIdx.y;
    const int tid = threadIdx.x;
    const int jbase = jc * JCHUNK;

    const float4* __restrict__ posj = (const float4*)(pos + jbase);
    for (int t = tid; t < JP; t += THREADS) {
        const float4 v = posj[t];            // {x0,y0,x1,y1}
        sx[t] = __floats2half2_rn(v.x, v.z);
        sy[t] = __floats2half2_rn(v.y, v.w);
    }
    __syncthreads();

    const int i0 = ib * (THREADS * IPT);
    const __half2 TT2 = __float2half2_rn(TT);

    __half2 hc[IPT], hs[IPT], ha[IPT], hct[IPT], hnst[IPT], hbt[IPT], cnth[IPT];
    float sum0[IPT], sum1[IPT];

    #pragma unroll
    for (int k = 0; k < IPT; k++) {
        const int i = i0 + k * THREADS + tid;
        const float2 p = pos[i];
        const float2 q = past[i];
        const float dx = p.x - q.x;
        const float dy = p.y - q.y;
        const float l2 = fmaf(dx, dx, dy * dy);
        float rin; asm("rsqrt.approx.f32 %0, %1;" : "=f"(rin) : "f"(l2));
        const float ci = (l2 > 0.0f) ? dx * rin : 1.0f;
        const float si = (l2 > 0.0f) ? dy * rin : 0.0f;
        const float av = -fmaf(p.x, ci, p.y * si);     // -(x c + y s)
        const float bv =  fmaf(p.x, si, -(p.y * ci));  //  x s - y c
        hc[k]   = __float2half2_rn(ci);
        hs[k]   = __float2half2_rn(si);
        ha[k]   = __float2half2_rn(av);
        hct[k]  = __float2half2_rn(ci * INVT);         // y-row scaled by 1/T
        hnst[k] = __float2half2_rn(-si * INVT);
        hbt[k]  = __float2half2_rn(bv * INVT);
        sum0[k] = 0.0f; sum1[k] = 0.0f;
        cnth[k] = __float2half2_rn(0.0f);
    }

    #pragma unroll 4
    for (int jj = 0; jj < JP; jj++) {
        const __half2 px = sx[jj];
        const __half2 py = sy[jj];
        #pragma unroll
        for (int k = 0; k < IPT; k++) {
            // xp = xj*c + yj*s + a ; yb = (y')/T -> arc test is |yb| < xp
            const __half2 xp = __hfma2(px, hc[k],  __hfma2(py, hs[k],   ha[k]));
            const __half2 yb = __hfma2(py, hct[k], __hfma2(px, hnst[k], hbt[k]));
            const __half2 mask = __hlt2(__habs2(yb), xp);          // {1,0}
            const __half2 sq = __hfma2(xp, xp, __hmul2(__hmul2(TT2, yb), yb));
            const __half2 sqm = __hmul2(sq, mask);                 // gated sq
            sum0[k] += sqa(__low2float(sqm));                      // sqrt(0)=0
            sum1[k] += sqa(__high2float(sqm));
            cnth[k] = __hadd2(cnth[k], mask);
        }
    }

    #pragma unroll
    for (int k = 0; k < IPT; k++) {
        const int i = i0 + k * THREADS + tid;
        float s0 = sum0[k], s1 = sum1[k];
        float cnt = __low2float(cnth[k]) + __high2float(cnth[k]);
        if (ib == jc) {
            // Remove self-pair: recompute the identical lanewise fp16 chain.
            const int loc = i - jbase;                 // = k*THREADS+tid
            const int m = loc >> 1, lane = loc & 1;
            const __half2 px = sx[m], py = sy[m];
            const __half2 xp = __hfma2(px, hc[k],  __hfma2(py, hs[k],   ha[k]));
            const __half2 yb = __hfma2(py, hct[k], __hfma2(px, hnst[k], hbt[k]));
            const __half2 mask = __hlt2(__habs2(yb), xp);
            const __half2 sq = __hfma2(xp, xp, __hmul2(__hmul2(TT2, yb), yb));
            const __half2 sqm = __hmul2(sq, mask);
            if (lane) { s1 -= sqa(__high2float(sqm)); cnt -= __high2float(mask); }
            else      { s0 -= sqa(__low2float(sqm));  cnt -= __low2float(mask);  }
        }
        g_part[i * JC + jc] = make_float2(s0 + s1, cnt);
    }
}

__global__ __launch_bounds__(128)
void finalize_kernel(const int* __restrict__ idxmask,
                     const float* __restrict__ radii,
                     float* __restrict__ out) {
    const int i = blockIdx.x * 128 + threadIdx.x;
    const float4* __restrict__ p = (const float4*)(g_part + i * JC);
    float s = 0.0f, c = 0.0f;
    #pragma unroll
    for (int q = 0; q < JC / 2; q++) {
        const float4 v = p[q];                 // {sum0, cnt0, sum1, cnt1}
        s += v.x + v.z;
        c += v.y + v.w;
    }
    float mean = (c > 0.0f) ? s / c : 0.0f;
    mean = fminf(fmaxf(mean, 0.2f), 5.0f);     // clip [MIN_D, MAX_D]
    const float reg = (mean - 0.2f) * (1.0f / 4.8f);
    const float r = fmaf(reg, 3.5f, 0.5f);     // MIN_R + reg*(MAX_R-MIN_R)
    out[i] = idxmask[i] ? r : radii[i];
}

extern "C" void kernel_launch(void* const* d_in, const int* in_sizes, int n_in,
                              void* d_out, int out_size) {
    const float2* past = (const float2*)d_in[0];
    const float2* pos  = (const float2*)d_in[1];
    const int* idxm    = (const int*)d_in[2];   // bool widened to int32
    const float* radii = (const float*)d_in[3];
    float* out = (float*)d_out;

    dim3 grid(IB, JC);
    pair_kernel<<<grid, THREADS>>>(past, pos);
    finalize_kernel<<<NP / 128, 128>>>(idxm, radii, out);
}

// round 6
// speedup vs baseline: 1.0237x; 1.0237x over previous
#include <cuda_runtime.h>

#define NP 8192
#define THREADS 256
#define IPT 4
#define IB (NP / (THREADS * IPT))   // 8 i-blocks (1024 i's each)
#define JC 74
#define JCHUNK 111                  // 74*111 = 8214 >= 8192

static_assert(IB * THREADS * IPT == NP, "i coverage");
static_assert(JC * JCHUNK >= NP, "j coverage");
static_assert(IB * JC == 592, "perfect wave: 148 SMs x 4 blocks");

// Scratch: [i][jc] -> {sum, cnt}; every slot written once per launch.
__device__ float2 g_part[NP * JC];

__device__ __forceinline__ float sqa(float x) {
    float r; asm("sqrt.approx.f32 %0, %1;" : "=f"(r) : "f"(x)); return r;
}

#define T35   0.70020753f   // tan(35 deg)
#define INVT  1.4281480f    // 1/tan(35 deg)
#define TT    0.49029058f   // tan^2(35 deg)

__global__ __launch_bounds__(THREADS, 4)
void pair_kernel(const float2* __restrict__ past, const float2* __restrict__ pos) {
    __shared__ float2 sj[JCHUNK];
    const int ib = blockIdx.x;
    const int jc = blockIdx.y;
    const int tid = threadIdx.x;
    const int jbase = jc * JCHUNK;
    const int jend = min(NP - jbase, JCHUNK);

    for (int t = tid; t < jend; t += THREADS) sj[t] = pos[jbase + t];
    __syncthreads();

    const int i0 = ib * (THREADS * IPT);

    float c_[IPT], s_[IPT], a_[IPT], ct_[IPT], nst_[IPT], bt_[IPT];
    float sum[IPT]; int cnt[IPT];

    #pragma unroll
    for (int k = 0; k < IPT; k++) {
        const int i = i0 + k * THREADS + tid;
        const float2 p = pos[i];
        const float2 q = past[i];
        const float dx = p.x - q.x;
        const float dy = p.y - q.y;
        const float l2 = fmaf(dx, dx, dy * dy);
        float rin; asm("rsqrt.approx.f32 %0, %1;" : "=f"(rin) : "f"(l2));
        const float ci = (l2 > 0.0f) ? dx * rin : 1.0f;
        const float si = (l2 > 0.0f) ? dy * rin : 0.0f;
        c_[k]  = ci;
        s_[k]  = si;
        a_[k]  = -fmaf(p.x, ci, p.y * si);          // -(x c + y s)
        const float bv = fmaf(p.x, si, -(p.y * ci)); //  x s - y c
        ct_[k]  =  ci * INVT;                        // y-row pre-divided by tan35:
        nst_[k] = -si * INVT;                        // arc test becomes |yb| < xp
        bt_[k]  =  bv * INVT;
        sum[k] = 0.0f; cnt[k] = 0;
    }

    for (int jj = 0; jj < jend; jj++) {
        const float2 pj = sj[jj];
        #pragma unroll
        for (int k = 0; k < IPT; k++) {
            const float xp = fmaf(pj.x, c_[k],  fmaf(pj.y, s_[k],   a_[k]));
            const float yb = fmaf(pj.y, ct_[k], fmaf(pj.x, nst_[k], bt_[k]));
            const float u  = TT * yb;
            const float sq = fmaf(u, yb, xp * xp);   // xp^2 + (tan35*yb)^2 = true dist^2
            const float d  = sqa(sq);
            if (fabsf(yb) < xp) { sum[k] += d; cnt[k]++; }   // implies xp > 0
        }
    }

    #pragma unroll
    for (int k = 0; k < IPT; k++) {
        const int i = i0 + k * THREADS + tid;
        float s = sum[k]; int c = cnt[k];
        // Self-pair may have slipped past the strict test (xp,yb ~ rounding noise).
        // Recompute its contribution with bitwise-identical arithmetic; subtract.
        if (i >= jbase && i < jbase + jend) {
            const float2 pj = sj[i - jbase];
            const float xp = fmaf(pj.x, c_[k],  fmaf(pj.y, s_[k],   a_[k]));
            const float yb = fmaf(pj.y, ct_[k], fmaf(pj.x, nst_[k], bt_[k]));
            const float u  = TT * yb;
            const float sq = fmaf(u, yb, xp * xp);
            const float d  = sqa(sq);
            if (fabsf(yb) < xp) { s -= d; c--; }
        }
        g_part[i * JC + jc] = make_float2(s, (float)c);
    }
}

__global__ __launch_bounds__(128)
void finalize_kernel(const int* __restrict__ idxmask,
                     const float* __restrict__ radii,
                     float* __restrict__ out) {
    const int i = blockIdx.x * 128 + threadIdx.x;
    const float4* __restrict__ p = (const float4*)(g_part + i * JC);
    float s = 0.0f, c = 0.0f;
    #pragma unroll
    for (int q = 0; q < JC / 2; q++) {
        const float4 v = p[q];                 // {sum0, cnt0, sum1, cnt1}
        s += v.x + v.z;
        c += v.y + v.w;
    }
    float mean = (c > 0.0f) ? s / c : 0.0f;
    mean = fminf(fmaxf(mean, 0.2f), 5.0f);     // clip [MIN_D, MAX_D]
    const float reg = (mean - 0.2f) * (1.0f / 4.8f);
    const float r = fmaf(reg, 3.5f, 0.5f);     // MIN_R + reg*(MAX_R-MIN_R)
    out[i] = idxmask[i] ? r : radii[i];
}

extern "C" void kernel_launch(void* const* d_in, const int* in_sizes, int n_in,
                              void* d_out, int out_size) {
    const float2* past = (const float2*)d_in[0];
    const float2* pos  = (const float2*)d_in[1];
    const int* idxm    = (const int*)d_in[2];   // bool widened to int32
    const float* radii = (const float*)d_in[3];
    float* out = (float*)d_out;

    dim3 grid(IB, JC);
    pair_kernel<<<grid, THREADS>>>(past, pos);
    finalize_kernel<<<NP / 128, 128>>>(idxm, radii, out);
}

// round 7
// speedup vs baseline: 1.2183x; 1.1901x over previous
#include <cuda_runtime.h>
#include <cuda_fp16.h>

#define NP 8192
#define THREADS 256
#define IPT 2
#define IB (NP / (THREADS * IPT))   // 16 i-blocks (512 i's each)
#define JC 37
#define JCHUNK 222                  // even; 37*222 = 8214 >= 8192; last chunk 200 (even)
#define JPMAX (JCHUNK / 2)          // 111 packed pairs

static_assert(IB * THREADS * IPT == NP, "i coverage");
static_assert(JC * JCHUNK >= NP, "j coverage");
static_assert(IB * JC == 592, "perfect wave: 148 SMs x 4 blocks");

// Scratch [jc][i]: coalesced writes from pair kernel, coalesced reads in finalize.
// Every slot written exactly once per launch.
__device__ float2 g_part[JC * NP];

__device__ __forceinline__ float sqa(float x) {
    float r; asm("sqrt.approx.f32 %0, %1;" : "=f"(r) : "f"(x)); return r;
}

#define T35   0.70020753f   // tan(35 deg)
#define INVT  1.4281480f    // 1/tan(35 deg)
#define TT    0.49029058f   // tan^2(35 deg)

struct h2pair { __half2 x, y; };   // 8 bytes -> one LDS.64

__global__ __launch_bounds__(THREADS, 4)
void pair_kernel(const float2* __restrict__ past, const float2* __restrict__ pos) {
    __shared__ h2pair sj[JPMAX];
    const int ib = blockIdx.x;
    const int jc = blockIdx.y;
    const int tid = threadIdx.x;
    const int jbase = jc * JCHUNK;
    const int jend = min(NP - jbase, JCHUNK);   // 222 or 200, always even
    const int jp = jend >> 1;

    const float4* __restrict__ posj4 = (const float4*)(pos + jbase);
    for (int t = tid; t < jp; t += THREADS) {
        const float4 v = posj4[t];               // {x0,y0,x1,y1}
        sj[t].x = __floats2half2_rn(v.x, v.z);
        sj[t].y = __floats2half2_rn(v.y, v.w);
    }
    __syncthreads();

    const int i0 = ib * (THREADS * IPT);
    const __half2 TT2 = __float2half2_rn(TT);

    __half2 hc[IPT], hs[IPT], ha[IPT], hct[IPT], hnst[IPT], hbt[IPT], cnth[IPT];
    float sum0[IPT], sum1[IPT];

    #pragma unroll
    for (int k = 0; k < IPT; k++) {
        const int i = i0 + k * THREADS + tid;
        const float2 p = pos[i];
        const float2 q = past[i];
        const float dx = p.x - q.x;
        const float dy = p.y - q.y;
        const float l2 = fmaf(dx, dx, dy * dy);
        float rin; asm("rsqrt.approx.f32 %0, %1;" : "=f"(rin) : "f"(l2));
        const float ci = (l2 > 0.0f) ? dx * rin : 1.0f;
        const float si = (l2 > 0.0f) ? dy * rin : 0.0f;
        const float av = -fmaf(p.x, ci, p.y * si);      // -(x c + y s)
        const float bv =  fmaf(p.x, si, -(p.y * ci));   //  x s - y c
        hc[k]   = __float2half2_rn(ci);
        hs[k]   = __float2half2_rn(si);
        ha[k]   = __float2half2_rn(av);
        hct[k]  = __float2half2_rn(ci * INVT);          // y-row / tan35:
        hnst[k] = __float2half2_rn(-si * INVT);         //   arc test |yb| < xp
        hbt[k]  = __float2half2_rn(bv * INVT);
        sum0[k] = 0.0f; sum1[k] = 0.0f;
        cnth[k] = __float2half2_rn(0.0f);
    }

    #pragma unroll 4
    for (int m = 0; m < jp; m++) {
        const __half2 px = sj[m].x;
        const __half2 py = sj[m].y;
        #pragma unroll
        for (int k = 0; k < IPT; k++) {
            const __half2 xp = __hfma2(px, hc[k],  __hfma2(py, hs[k],   ha[k]));
            const __half2 yb = __hfma2(py, hct[k], __hfma2(px, hnst[k], hbt[k]));
            const __half2 mask = __hlt2(__habs2(yb), xp);            // {1,0}; xp>0 implied
            const __half2 sq = __hfma2(xp, xp, __hmul2(__hmul2(yb, yb), TT2));
            const __half2 sqm = __hmul2(sq, mask);                   // gated: sqrt(0)=0
            sum0[k] += sqa(__low2float(sqm));
            sum1[k] += sqa(__high2float(sqm));
            cnth[k] = __hadd2(cnth[k], mask);
        }
    }

    #pragma unroll
    for (int k = 0; k < IPT; k++) {
        const int i = i0 + k * THREADS + tid;
        float s0 = sum0[k], s1 = sum1[k];
        float cnt = __low2float(cnth[k]) + __high2float(cnth[k]);
        if (i >= jbase && i < jbase + jend) {
            // Remove self-pair via bitwise-identical lanewise recompute.
            const int loc = i - jbase;
            const int m = loc >> 1, lane = loc & 1;
            const __half2 px = sj[m].x, py = sj[m].y;
            const __half2 xp = __hfma2(px, hc[k],  __hfma2(py, hs[k],   ha[k]));
            const __half2 yb = __hfma2(py, hct[k], __hfma2(px, hnst[k], hbt[k]));
            const __half2 mask = __hlt2(__habs2(yb), xp);
            const __half2 sq = __hfma2(xp, xp, __hmul2(__hmul2(yb, yb), TT2));
            const __half2 sqm = __hmul2(sq, mask);
            if (lane) { s1 -= sqa(__high2float(sqm)); cnt -= __high2float(mask); }
            else      { s0 -= sqa(__low2float(sqm));  cnt -= __low2float(mask);  }
        }
        g_part[jc * NP + i] = make_float2(s0 + s1, cnt);   // coalesced
    }
}

__global__ __launch_bounds__(256)
void finalize_kernel(const int* __restrict__ idxmask,
                     const float* __restrict__ radii,
                     float* __restrict__ out) {
    const int i = blockIdx.x * 256 + threadIdx.x;
    float s = 0.0f, c = 0.0f;
    #pragma unroll
    for (int q = 0; q < JC; q++) {
        const float2 v = g_part[q * NP + i];   // coalesced LDG.64, high MLP
        s += v.x;
        c += v.y;
    }
    float mean = (c > 0.0f) ? s / c : 0.0f;
    mean = fminf(fmaxf(mean, 0.2f), 5.0f);     // clip [MIN_D, MAX_D]
    const float reg = (mean - 0.2f) * (1.0f / 4.8f);
    const float r = fmaf(reg, 3.5f, 0.5f);     // MIN_R + reg*(MAX_R-MIN_R)
    out[i] = idxmask[i] ? r : radii[i];
}

extern "C" void kernel_launch(void* const* d_in, const int* in_sizes, int n_in,
                              void* d_out, int out_size) {
    const float2* past = (const float2*)d_in[0];
    const float2* pos  = (const float2*)d_in[1];
    const int* idxm    = (const int*)d_in[2];   // bool widened to int32
    const float* radii = (const float*)d_in[3];
    float* out = (float*)d_out;

    dim3 grid(IB, JC);
    pair_kernel<<<grid, THREADS>>>(past, pos);
    finalize_kernel<<<NP / 256, 256>>>(idxm, radii, out);
}

// round 8
// speedup vs baseline: 1.2901x; 1.0589x over previous
#include <cuda_runtime.h>
#include <cuda_fp16.h>

#define NP 8192
#define THREADS 256
#define IPT 2
#define IB (NP / (THREADS * IPT))   // 16 i-blocks
#define JC 37
#define JCHUNK 222                  // even; last chunk 200 (even)
#define JPMAX (JCHUNK / 2)

static_assert(IB * THREADS * IPT == NP, "i coverage");
static_assert(JC * JCHUNK >= NP, "j coverage");
static_assert(IB * JC == 592, "perfect wave: 148 SMs x 4 blocks");

// Scratch [jc][i]: coalesced both sides; every slot written once per launch.
__device__ float2 g_part[JC * NP];

__device__ __forceinline__ float sqa(float x) {
    float r; asm("sqrt.approx.f32 %0, %1;" : "=f"(r) : "f"(x)); return r;
}
__device__ __forceinline__ unsigned h2u(__half2 h) {
    return *reinterpret_cast<const unsigned*>(&h);
}

#define T35   0.70020753f   // tan(35 deg)
#define INVT  1.4281480f    // 1/tan(35 deg)
#define TT    0.49029058f   // tan^2(35 deg)

struct h2pair { __half2 x, y; };

__global__ __launch_bounds__(THREADS, 4)
void pair_kernel(const float2* __restrict__ past, const float2* __restrict__ pos) {
    __shared__ h2pair sj[JPMAX];
    const int ib = blockIdx.x;
    const int jc = blockIdx.y;
    const int tid = threadIdx.x;
    const int jbase = jc * JCHUNK;
    const int jend = min(NP - jbase, JCHUNK);   // 222 or 200
    const int jp = jend >> 1;

    const float4* __restrict__ posj4 = (const float4*)(pos + jbase);
    for (int t = tid; t < jp; t += THREADS) {
        const float4 v = posj4[t];
        sj[t].x = __floats2half2_rn(v.x, v.z);
        sj[t].y = __floats2half2_rn(v.y, v.w);
    }
    __syncthreads();

    const int i0 = ib * (THREADS * IPT);
    const __half2 TT2 = __float2half2_rn(TT);

    __half2 hc[IPT], hs[IPT], ha[IPT], hct[IPT], hnst[IPT], hbt[IPT];
    float sum0[IPT], sum1[IPT];
    int cnt0[IPT], cnt1[IPT];

    #pragma unroll
    for (int k = 0; k < IPT; k++) {
        const int i = i0 + k * THREADS + tid;
        const float2 p = pos[i];
        const float2 q = past[i];
        const float dx = p.x - q.x;
        const float dy = p.y - q.y;
        const float l2 = fmaf(dx, dx, dy * dy);
        float rin; asm("rsqrt.approx.f32 %0, %1;" : "=f"(rin) : "f"(l2));
        const float ci = (l2 > 0.0f) ? dx * rin : 1.0f;
        const float si = (l2 > 0.0f) ? dy * rin : 0.0f;
        const float av = -fmaf(p.x, ci, p.y * si);      // -(x c + y s)
        const float bv =  fmaf(p.x, si, -(p.y * ci));   //  x s - y c
        hc[k]   = __float2half2_rn(ci);
        hs[k]   = __float2half2_rn(si);
        ha[k]   = __float2half2_rn(av);
        hct[k]  = __float2half2_rn(ci * INVT);          // y-row / tan35:
        hnst[k] = __float2half2_rn(-si * INVT);         //   arc test |yb| < xp
        hbt[k]  = __float2half2_rn(bv * INVT);
        sum0[k] = 0.0f; sum1[k] = 0.0f;
        cnt0[k] = 0; cnt1[k] = 0;
    }

    #pragma unroll 4
    for (int m = 0; m < jp; m++) {
        const __half2 px = sj[m].x;
        const __half2 py = sj[m].y;
        #pragma unroll
        for (int k = 0; k < IPT; k++) {
            const __half2 xp = __hfma2(px, hc[k],  __hfma2(py, hs[k],   ha[k]));
            const __half2 yb = __hfma2(py, hct[k], __hfma2(px, hnst[k], hbt[k]));
            const __half2 sq = __hfma2(xp, xp, __hmul2(__hmul2(yb, yb), TT2));
            const float dl = sqa(__low2float(sq));
            const float dh = sqa(__high2float(sq));
            // dual-predicate arc test: p=(|yb|.lo<xp.lo), q=(.hi); xp>0 implied
            asm volatile(
                "{\n\t"
                ".reg .pred p, q;\n\t"
                "setp.lt.f16x2 p|q, %4, %5;\n\t"
                "@p add.f32 %0, %0, %6;\n\t"
                "@q add.f32 %1, %1, %7;\n\t"
                "@p add.s32 %2, %2, 1;\n\t"
                "@q add.s32 %3, %3, 1;\n\t"
                "}"
                : "+f"(sum0[k]), "+f"(sum1[k]), "+r"(cnt0[k]), "+r"(cnt1[k])
                : "r"(h2u(__habs2(yb))), "r"(h2u(xp)), "f"(dl), "f"(dh));
        }
    }

    #pragma unroll
    for (int k = 0; k < IPT; k++) {
        const int i = i0 + k * THREADS + tid;
        float s0 = sum0[k], s1 = sum1[k];
        int c0 = cnt0[k], c1 = cnt1[k];
        if (i >= jbase && i < jbase + jend) {
            // Remove self-pair via identical lanewise recompute.
            const int loc = i - jbase;
            const int m = loc >> 1, lane = loc & 1;
            const __half2 px = sj[m].x, py = sj[m].y;
            const __half2 xp = __hfma2(px, hc[k],  __hfma2(py, hs[k],   ha[k]));
            const __half2 yb = __hfma2(py, hct[k], __hfma2(px, hnst[k], hbt[k]));
            const __half2 sq = __hfma2(xp, xp, __hmul2(__hmul2(yb, yb), TT2));
            const float dl = sqa(__low2float(sq));
            const float dh = sqa(__high2float(sq));
            unsigned ayb = h2u(__habs2(yb)), xpb = h2u(xp);
            int rl = 0, rh = 0;
            asm volatile(
                "{\n\t"
                ".reg .pred p, q;\n\t"
                "setp.lt.f16x2 p|q, %2, %3;\n\t"
                "selp.b32 %0, 1, 0, p;\n\t"
                "selp.b32 %1, 1, 0, q;\n\t"
                "}"
                : "=r"(rl), "=r"(rh) : "r"(ayb), "r"(xpb));
            if (lane) { if (rh) { s1 -= dh; c1--; } }
            else      { if (rl) { s0 -= dl; c0--; } }
        }
        g_part[jc * NP + i] = make_float2(s0 + s1, (float)(c0 + c1));   // coalesced
    }
}

// 4 threads per row: tid = t*64 + iloc (t = tid>>6) keeps LDG coalesced
// (warp = 32 consecutive iloc at fixed t). Cross-t reduce via shared memory.
__global__ __launch_bounds__(256)
void finalize_kernel(const int* __restrict__ idxmask,
                     const float* __restrict__ radii,
                     float* __restrict__ out) {
    __shared__ float2 red[256];
    const int tid = threadIdx.x;
    const int t = tid >> 6;           // 0..3
    const int iloc = tid & 63;
    const int i = blockIdx.x * 64 + iloc;

    float s = 0.0f, c = 0.0f;
    #pragma unroll
    for (int q = t; q < JC; q += 4) {
        const float2 v = g_part[q * NP + i];
        s += v.x;
        c += v.y;
    }
    red[tid] = make_float2(s, c);
    __syncthreads();
    if (tid < 64) {
        float2 a = red[tid], b = red[tid + 64], d = red[tid + 128], e = red[tid + 192];
        s = a.x + b.x + d.x + e.x;
        c = a.y + b.y + d.y + e.y;
        float mean = (c > 0.0f) ? s / c : 0.0f;
        mean = fminf(fmaxf(mean, 0.2f), 5.0f);         // clip [MIN_D, MAX_D]
        const float reg = (mean - 0.2f) * (1.0f / 4.8f);
        const float r = fmaf(reg, 3.5f, 0.5f);          // MIN_R + reg*(MAX_R-MIN_R)
        out[i] = idxmask[i] ? r : radii[i];
    }
}

extern "C" void kernel_launch(void* const* d_in, const int* in_sizes, int n_in,
                              void* d_out, int out_size) {
    const float2* past = (const float2*)d_in[0];
    const float2* pos  = (const float2*)d_in[1];
    const int* idxm    = (const int*)d_in[2];   // bool widened to int32
    const float* radii = (const float*)d_in[3];
    float* out = (float*)d_out;

    dim3 grid(IB, JC);
    pair_kernel<<<grid, THREADS>>>(past, pos);
    finalize_kernel<<<NP / 64, 256>>>(idxm, radii, out);
}